// round 13
// baseline (speedup 1.0000x reference)
#include <cuda_runtime.h>
#include <cuda_bf16.h>
#include <math.h>
#include <stdint.h>

// Problem: B=4, S=1024, D=1024, H=16, DK=64
#define SEQ   1024
#define BATCH 4
#define DIM   1024
#define HEADS 16
#define DKH   64
#define MROWS (BATCH * SEQ)   // 4096

__device__ __forceinline__ uint32_t smem_to_u32(const void* p) {
    uint32_t a;
    asm("{ .reg .u64 t; cvta.to.shared.u64 t, %1; cvt.u32.u64 %0, t; }" : "=r"(a) : "l"(p));
    return a;
}
__device__ __forceinline__ uint32_t pk_bf16(__nv_bfloat16 a, __nv_bfloat16 b) {
    return (uint32_t)__bfloat16_as_ushort(a) | ((uint32_t)__bfloat16_as_ushort(b) << 16);
}
__device__ __forceinline__ void mma_bf16(float* d, const uint32_t* a, const uint32_t* b) {
    asm volatile("mma.sync.aligned.m16n8k16.row.col.f32.bf16.bf16.f32 "
        "{%0,%1,%2,%3}, {%4,%5,%6,%7}, {%8,%9}, {%0,%1,%2,%3};"
        : "+f"(d[0]), "+f"(d[1]), "+f"(d[2]), "+f"(d[3])
        : "r"(a[0]), "r"(a[1]), "r"(a[2]), "r"(a[3]), "r"(b[0]), "r"(b[1]));
}
__device__ __forceinline__ void ldsm4(uint32_t addr, uint32_t* r) {
    asm volatile("ldmatrix.sync.aligned.m8n8.x4.shared.b16 {%0,%1,%2,%3}, [%4];"
        : "=r"(r[0]), "=r"(r[1]), "=r"(r[2]), "=r"(r[3]) : "r"(addr));
}
#define CP_ASYNC16(saddr, gaddr) \
    asm volatile("cp.async.cg.shared.global [%0], [%1], 16;" :: "r"(saddr), "l"(gaddr) : "memory")
#define CP_COMMIT() asm volatile("cp.async.commit_group;" ::: "memory")
#define CP_WAIT1()  asm volatile("cp.async.wait_group 1;" ::: "memory")

// ================= scratch (referenced ONLY inside device code) =================
__device__ __align__(256) __nv_bfloat16 Xh_buf[MROWS * DIM];
__device__ __align__(256) __nv_bfloat16 Xl_buf[MROWS * DIM];
__device__ __align__(256) __nv_bfloat16 gh_buf[MROWS * DIM];
__device__ __align__(256) __nv_bfloat16 gl_buf[MROWS * DIM];
__device__ __align__(256) __nv_bfloat16 WGt_h[DIM * DIM];
__device__ __align__(256) __nv_bfloat16 WGt_l[DIM * DIM];
__device__ __align__(256) __nv_bfloat16 Wkt_h[DIM * DIM];
__device__ __align__(256) __nv_bfloat16 Wkt_l[DIM * DIM];
__device__ __align__(256) float kw_buf[MROWS * DIM];
__device__ __align__(256) float g0_buf[BATCH * DIM];
__device__ __align__(256) float q0_part[32 * BATCH * DIM];
__device__ __align__(256) float q0_buf[BATCH * DIM];
__device__ __align__(256) float sc_buf[BATCH * HEADS * SEQ];
__device__ __align__(256) float row0_buf[BATCH * HEADS * SEQ];
__device__ __align__(256) float cos_tab[SEQ * 32];
__device__ __align__(256) float sin_tab[SEQ * 32];

// ================= RoPE tables =================
__global__ void rope_tables_kernel() {
    int s = blockIdx.x;
    int j = threadIdx.x;                 // 0..31
    float inv = powf(10000.0f, -((float)j) / 32.0f);
    float ang = (float)s * inv;
    cos_tab[s * 32 + j] = cosf(ang);
    sin_tab[s * 32 + j] = sinf(ang);
}

// ============ weight transpose + hi/lo split:  Wt[n][k] = split(W[k][n]) ============
template <int WHICH>
__global__ __launch_bounds__(256) void convW_kernel(const float* __restrict__ W)
{
    __nv_bfloat16* Th = (WHICH == 0) ? WGt_h : Wkt_h;
    __nv_bfloat16* Tl = (WHICH == 0) ? WGt_l : Wkt_l;
    __shared__ float tile[32][33];
    int tx = threadIdx.x, ty = threadIdx.y;      // block (32, 8)
    int k0 = blockIdx.y * 32, n0 = blockIdx.x * 32;
    #pragma unroll
    for (int j = 0; j < 32; j += 8)
        tile[ty + j][tx] = W[(size_t)(k0 + ty + j) * DIM + n0 + tx];
    __syncthreads();
    #pragma unroll
    for (int j = 0; j < 32; j += 8) {
        float v = tile[tx][ty + j];
        __nv_bfloat16 h = __float2bfloat16(v);
        __nv_bfloat16 l = __float2bfloat16(v - __bfloat162float(h));
        size_t o = (size_t)(n0 + ty + j) * DIM + k0 + tx;
        Th[o] = h; Tl[o] = l;
    }
}

// ============ X hi/lo split (elementwise) ============
__global__ __launch_bounds__(256) void convX_kernel(const float* __restrict__ X)
{
    int idx = blockIdx.x * 256 + threadIdx.x;    // over MROWS*DIM/4
    float4 v = ((const float4*)X)[idx];
    __nv_bfloat16 h0 = __float2bfloat16(v.x), h1 = __float2bfloat16(v.y);
    __nv_bfloat16 h2 = __float2bfloat16(v.z), h3 = __float2bfloat16(v.w);
    __nv_bfloat16 l0 = __float2bfloat16(v.x - __bfloat162float(h0));
    __nv_bfloat16 l1 = __float2bfloat16(v.y - __bfloat162float(h1));
    __nv_bfloat16 l2 = __float2bfloat16(v.z - __bfloat162float(h2));
    __nv_bfloat16 l3 = __float2bfloat16(v.w - __bfloat162float(h3));
    ((uint2*)Xh_buf)[idx] = make_uint2(pk_bf16(h0, h1), pk_bf16(h2, h3));
    ((uint2*)Xl_buf)[idx] = make_uint2(pk_bf16(l0, l1), pk_bf16(l2, l3));
}

// ================= mma.sync split-bf16 GEMM, 3-stage cp.async + ldmatrix =================
// C[4096,1024] = (Ah+Al) x (Bh+Bl)^T  (B stored [N][K] K-major), fp32 accum.
// 3 passes per acc: Ah*Bh + Al*Bh + Ah*Bl (same per-acc order as before).
// CTA tile 128(M) x 64(N), k-tile 32. 3 stages x 24KB, 3 CTAs/SM (24 warps).
// Stage layout (words): Ah[0..2047] Al[2048..4095] Bh[4096..5119] Bl[5120..6143]
#define STAGE_WORDS 6144      // 24KB per stage
#define NSTAGE 3

template <int PHASE>
__global__ __launch_bounds__(256, 3) void gemm_kernel(const float* __restrict__ bias)
{
    extern __shared__ __align__(16) uint32_t s32[];     // 3 x 6144 words
    const uint32_t sbu = smem_to_u32(s32);
    const int tid = threadIdx.x;
    const int wid = tid >> 5, lane = tid & 31;
    const int gID = lane >> 2, tig = lane & 3;
    const int m0 = blockIdx.y * 128, n0 = blockIdx.x * 64;
    const int wm = (wid & 3) * 32, wn = (wid >> 2) * 32;

    const __nv_bfloat16* gptr[4];
    if (PHASE == 0) {
        gptr[0] = Xh_buf + (size_t)m0 * DIM;  gptr[1] = Xl_buf + (size_t)m0 * DIM;
        gptr[2] = WGt_h  + (size_t)n0 * DIM;  gptr[3] = WGt_l  + (size_t)n0 * DIM;
    } else {
        gptr[0] = gh_buf + (size_t)m0 * DIM;  gptr[1] = gl_buf + (size_t)m0 * DIM;
        gptr[2] = Wkt_h  + (size_t)n0 * DIM;  gptr[3] = Wkt_l  + (size_t)n0 * DIM;
    }

    // stage copy: 1536 uint4 over 256 threads = 6 slots/thread, coords recomputed per call
    auto load_stage = [&](int buf, int t) {
        const int k0 = t * 32;
        #pragma unroll
        for (int p = 0; p < 6; p++) {
            int cid = p * 256 + tid;           // 0..1535
            int ten, row, ch, base;
            if (cid < 1024) {                  // A tensors: 512 chunks each
                ten = cid >> 9;                // 0 or 1
                int rc = cid & 511;
                row = rc >> 2; ch = rc & 3;
                base = ten * 2048;
            } else {                           // B tensors: 256 chunks each
                int bc = cid - 1024;
                ten = 2 + (bc >> 8);
                int rc = bc & 255;
                row = rc >> 2; ch = rc & 3;
                base = 4096 + (ten - 2) * 1024;
            }
            int pc = ch ^ ((row >> 1) & 3);    // swizzled 16B chunk
            uint32_t sa = sbu + (buf * STAGE_WORDS + base) * 4 + row * 64 + pc * 16;
            CP_ASYNC16(sa, gptr[ten] + (size_t)row * DIM + k0 + ch * 8);
        }
    };

    // ldmatrix per-lane coords (mat = lane>>3):
    const int mat = lane >> 3;
    const int a_rr = (lane & 7) + ((mat & 1) << 3);
    const int a_cs = mat >> 1;
    const int b_rr = (lane & 7) + ((mat >> 1) << 3);
    const int b_cs = mat & 1;

    float acc[2][4][4] = {};

    load_stage(0, 0); CP_COMMIT();
    load_stage(1, 1); CP_COMMIT();

    for (int t = 0; t < 32; t++) {
        CP_WAIT1();                       // stage t resident (t+1 may be in flight)
        __syncthreads();
        if (t + 2 < 32) load_stage((t + 2) % NSTAGE, t + 2);
        CP_COMMIT();                      // commit every iter (empty at tail) for group math

        const uint32_t stAh = sbu + ((t % NSTAGE) * STAGE_WORDS) * 4;
        const uint32_t stAl = stAh + 2048 * 4;
        const uint32_t stBh = stAh + 4096 * 4;
        const uint32_t stBl = stAh + 5120 * 4;

        #pragma unroll
        for (int kb = 0; kb < 2; kb++) {
            // A fragments: 2 mi x 2 tensors
            uint32_t afh[2][4], afl[2][4];
            #pragma unroll
            for (int mi = 0; mi < 2; mi++) {
                int ra = wm + mi * 16 + a_rr;
                uint32_t ch = (uint32_t)(((kb << 1) + a_cs) ^ ((ra >> 1) & 3));
                uint32_t off = (uint32_t)ra * 64 + (ch << 4);
                ldsm4(stAh + off, afh[mi]);
                ldsm4(stAl + off, afl[mi]);
            }
            // B fragments per nj; 3 pass-sweeps of 4 mma each
            #pragma unroll
            for (int nj = 0; nj < 2; nj++) {
                int rb = wn + nj * 16 + b_rr;
                uint32_t ch = (uint32_t)(((kb << 1) + b_cs) ^ ((rb >> 1) & 3));
                uint32_t off = (uint32_t)rb * 64 + (ch << 4);
                uint32_t bhq[4], blq[4];
                ldsm4(stBh + off, bhq);
                ldsm4(stBl + off, blq);
                // pass 1: afh x bh
                #pragma unroll
                for (int hf = 0; hf < 2; hf++)
                    #pragma unroll
                    for (int mi = 0; mi < 2; mi++)
                        mma_bf16(acc[mi][nj * 2 + hf], afh[mi], bhq + hf * 2);
                // pass 2: afl x bh
                #pragma unroll
                for (int hf = 0; hf < 2; hf++)
                    #pragma unroll
                    for (int mi = 0; mi < 2; mi++)
                        mma_bf16(acc[mi][nj * 2 + hf], afl[mi], bhq + hf * 2);
                // pass 3: afh x bl
                #pragma unroll
                for (int hf = 0; hf < 2; hf++)
                    #pragma unroll
                    for (int mi = 0; mi < 2; mi++)
                        mma_bf16(acc[mi][nj * 2 + hf], afh[mi], blq + hf * 2);
            }
        }
    }

    // ---- epilogue: acc[mi][j][*] -> rows wm+mi*16+gID(+8), cols wn+j*8+tig*2(,+1)
    #pragma unroll
    for (int mi = 0; mi < 2; mi++) {
        #pragma unroll
        for (int j = 0; j < 4; j++) {
            int n = n0 + wn + j * 8 + tig * 2;
            #pragma unroll
            for (int hh = 0; hh < 2; hh++) {
                int row = m0 + wm + mi * 16 + gID + hh * 8;
                float v0 = acc[mi][j][hh * 2]     + bias[n];
                float v1 = acc[mi][j][hh * 2 + 1] + bias[n + 1];
                if (PHASE == 0) {
                    __nv_bfloat16 h0 = __float2bfloat16(v0), h1 = __float2bfloat16(v1);
                    __nv_bfloat16 l0 = __float2bfloat16(v0 - __bfloat162float(h0));
                    __nv_bfloat16 l1 = __float2bfloat16(v1 - __bfloat162float(h1));
                    *(uint32_t*)&gh_buf[(size_t)row * DIM + n] = pk_bf16(h0, h1);
                    *(uint32_t*)&gl_buf[(size_t)row * DIM + n] = pk_bf16(l0, l1);
                    if ((row & (SEQ - 1)) == 0) {
                        g0_buf[(row >> 10) * DIM + n]     = v0;
                        g0_buf[(row >> 10) * DIM + n + 1] = v1;
                    }
                } else {
                    int s = row & (SEQ - 1);
                    int jj = (n & (DKH - 1)) >> 1;
                    float cs = cos_tab[s * 32 + jj];
                    float sn = sin_tab[s * 32 + jj];
                    *(float2*)&kw_buf[(size_t)row * DIM + n] =
                        make_float2(v0 * cs - v1 * sn, v1 * cs + v0 * sn);
                }
            }
        }
    }
}

// ============ q0 = g0 @ Wq (split-K x32 partials), fp32 ============
__global__ __launch_bounds__(256) void q0_part_kernel(const float* __restrict__ Wq)
{
    __shared__ float gs[32];
    int b = blockIdx.z, ks = blockIdx.y, cb = blockIdx.x;
    int col = cb * 256 + threadIdx.x;
    if (threadIdx.x < 32) gs[threadIdx.x] = g0_buf[b * DIM + ks * 32 + threadIdx.x];
    __syncthreads();
    float a = 0.f;
    #pragma unroll
    for (int i = 0; i < 32; i++)
        a += gs[i] * Wq[(size_t)(ks * 32 + i) * DIM + col];
    q0_part[(ks * BATCH + b) * DIM + col] = a;
}
__global__ __launch_bounds__(256) void q0_reduce_kernel(const float* __restrict__ bq)
{
    int idx = blockIdx.x * 256 + threadIdx.x;    // 0..4095
    int b = idx >> 10, col = idx & (DIM - 1);
    float a = bq[col];
    #pragma unroll
    for (int ks = 0; ks < 32; ks++) a += q0_part[(ks * BATCH + b) * DIM + col];
    q0_buf[idx] = a;
}

// ============ scores (parallel over 512 CTAs) ============
__global__ __launch_bounds__(256) void scores_kernel(const int* __restrict__ mask)
{
    int bh = blockIdx.y, seg = blockIdx.x;
    int b = bh >> 4, h = bh & 15;
    __shared__ float q0s[DKH];
    int tid = threadIdx.x;
    if (tid < DKH) q0s[tid] = q0_buf[b * DIM + h * DKH + tid];
    __syncthreads();
    int lane = tid & 31, warp = tid >> 5;
    #pragma unroll 4
    for (int i = 0; i < 16; i++) {
        int s = seg * 128 + i * 8 + warp;
        const float* kr = kw_buf + ((size_t)(b * SEQ + s)) * DIM + h * DKH;
        float v = q0s[lane] * kr[lane] + q0s[lane + 32] * kr[lane + 32];
        #pragma unroll
        for (int o = 16; o; o >>= 1) v += __shfl_down_sync(0xffffffffu, v, o);
        if (lane == 0) {
            float sv = v * 0.125f;   // 1/sqrt(64)
            if (mask[b * SEQ + s] == 0) sv = -1e9f;
            sc_buf[bh * SEQ + s] = sv;
        }
    }
}

// ============ softmax over 1024 ============
__global__ __launch_bounds__(256) void softmax_kernel()
{
    int bh = blockIdx.x;
    __shared__ float sc[SEQ];
    __shared__ float red[256];
    int tid = threadIdx.x;
    float m = -1e30f;
    for (int i = tid; i < SEQ; i += 256) { float v = sc_buf[bh * SEQ + i]; sc[i] = v; m = fmaxf(m, v); }
    red[tid] = m; __syncthreads();
    for (int o = 128; o; o >>= 1) { if (tid < o) red[tid] = fmaxf(red[tid], red[tid + o]); __syncthreads(); }
    m = red[0]; __syncthreads();
    float sum = 0.f;
    for (int i = tid; i < SEQ; i += 256) { float e = expf(sc[i] - m); sc[i] = e; sum += e; }
    red[tid] = sum; __syncthreads();
    for (int o = 128; o; o >>= 1) { if (tid < o) red[tid] += red[tid + o]; __syncthreads(); }
    float inv = 1.0f / red[0];
    for (int i = tid; i < SEQ; i += 256) row0_buf[bh * SEQ + i] = sc[i] * inv;
}

// ============ conv1d(k=3, 16->1024) + bias + relu ============
__global__ __launch_bounds__(256) void conv_kernel(const float* __restrict__ conv_w,
                                                   const float* __restrict__ conv_b,
                                                   float* __restrict__ out)
{
    int b  = blockIdx.z;
    int o0 = blockIdx.y * 64;
    int s0 = blockIdx.x * 512;
    __shared__ float ws[64 * 48];
    __shared__ float bs[64];
    int tid = threadIdx.x;
    for (int idx = tid; idx < 64 * 48; idx += 256) ws[idx] = conv_w[o0 * 48 + idx];
    if (tid < 64) bs[tid] = conv_b[o0 + tid];
    __syncthreads();
    int s = s0 + tid * 2;
    float r[16][4];
    #pragma unroll
    for (int i = 0; i < 16; i++) {
        const float* rp = row0_buf + (b * HEADS + i) * SEQ;
        r[i][0] = (s == 0) ? 0.f : rp[s - 1];
        r[i][1] = rp[s];
        r[i][2] = rp[s + 1];
        r[i][3] = (s + 2 > SEQ - 1) ? 0.f : rp[s + 2];
    }
    for (int o = 0; o < 64; o++) {
        float a0 = bs[o], a1 = bs[o];
        const float* w = &ws[o * 48];
        #pragma unroll
        for (int i = 0; i < 16; i++) {
            float w0 = w[i*3], w1 = w[i*3+1], w2 = w[i*3+2];
            a0 += r[i][0]*w0 + r[i][1]*w1 + r[i][2]*w2;
            a1 += r[i][1]*w0 + r[i][2]*w1 + r[i][3]*w2;
        }
        *(float2*)&out[((size_t)(b * DIM) + (o0 + o)) * SEQ + s] =
            make_float2(fmaxf(a0, 0.f), fmaxf(a1, 0.f));
    }
}

// ================= launch =================
#define GSMEM (NSTAGE * STAGE_WORDS * 4)   // 73728 bytes

extern "C" void kernel_launch(void* const* d_in, const int* in_sizes, int n_in,
                              void* d_out, int out_size)
{
    const float* X      = (const float*)d_in[0];
    const int*   mask   = (const int*)  d_in[1];
    const float* W_G    = (const float*)d_in[2];
    const float* b_G    = (const float*)d_in[3];
    const float* Wq     = (const float*)d_in[4];
    const float* bq     = (const float*)d_in[5];
    const float* Wk     = (const float*)d_in[6];
    const float* bk     = (const float*)d_in[7];
    const float* conv_w = (const float*)d_in[8];
    const float* conv_b = (const float*)d_in[9];
    float* out = (float*)d_out;

    cudaFuncSetAttribute(gemm_kernel<0>, cudaFuncAttributeMaxDynamicSharedMemorySize, GSMEM);
    cudaFuncSetAttribute(gemm_kernel<1>, cudaFuncAttributeMaxDynamicSharedMemorySize, GSMEM);

    // order chosen so gemm_kernel<0> is the 4th launch (the one ncu captures)
    convW_kernel<0><<<dim3(DIM/32, DIM/32), dim3(32, 8)>>>(W_G);
    convW_kernel<1><<<dim3(DIM/32, DIM/32), dim3(32, 8)>>>(Wk);
    convX_kernel<<<MROWS * DIM / 4 / 256, 256>>>(X);
    gemm_kernel<0><<<dim3(DIM/64, MROWS/128), 256, GSMEM>>>(b_G);
    rope_tables_kernel<<<SEQ, 32>>>();
    gemm_kernel<1><<<dim3(DIM/64, MROWS/128), 256, GSMEM>>>(bk);

    q0_part_kernel<<<dim3(DIM/256, 32, BATCH), 256>>>(Wq);
    q0_reduce_kernel<<<BATCH * DIM / 256, 256>>>(bq);
    scores_kernel<<<dim3(SEQ/128, BATCH*HEADS), 256>>>(mask);
    softmax_kernel<<<BATCH * HEADS, 256>>>();
    conv_kernel<<<dim3(SEQ/512, DIM/64, BATCH), 256>>>(conv_w, conv_b, out);
}

// round 15
// speedup vs baseline: 1.3208x; 1.3208x over previous
#include <cuda_runtime.h>
#include <cuda_bf16.h>
#include <cuda_fp16.h>
#include <math.h>
#include <stdint.h>

// Problem: B=4, S=1024, D=1024, H=16, DK=64
#define SEQ   1024
#define BATCH 4
#define DIM   1024
#define HEADS 16
#define DKH   64
#define MROWS (BATCH * SEQ)   // 4096

__device__ __forceinline__ uint32_t smem_to_u32(const void* p) {
    uint32_t a;
    asm("{ .reg .u64 t; cvta.to.shared.u64 t, %1; cvt.u32.u64 %0, t; }" : "=r"(a) : "l"(p));
    return a;
}
__device__ __forceinline__ uint32_t pk_f16(__half a, __half b) {
    return (uint32_t)__half_as_ushort(a) | ((uint32_t)__half_as_ushort(b) << 16);
}
__device__ __forceinline__ void mma_f16(float* d, const uint32_t* a, const uint32_t* b) {
    asm volatile("mma.sync.aligned.m16n8k16.row.col.f32.f16.f16.f32 "
        "{%0,%1,%2,%3}, {%4,%5,%6,%7}, {%8,%9}, {%0,%1,%2,%3};"
        : "+f"(d[0]), "+f"(d[1]), "+f"(d[2]), "+f"(d[3])
        : "r"(a[0]), "r"(a[1]), "r"(a[2]), "r"(a[3]), "r"(b[0]), "r"(b[1]));
}
__device__ __forceinline__ void ldsm4(uint32_t addr, uint32_t* r) {
    asm volatile("ldmatrix.sync.aligned.m8n8.x4.shared.b16 {%0,%1,%2,%3}, [%4];"
        : "=r"(r[0]), "=r"(r[1]), "=r"(r[2]), "=r"(r[3]) : "r"(addr));
}
#define CP_ASYNC16(saddr, gaddr) \
    asm volatile("cp.async.cg.shared.global [%0], [%1], 16;" :: "r"(saddr), "l"(gaddr) : "memory")
#define CP_COMMIT() asm volatile("cp.async.commit_group;" ::: "memory")
#define CP_WAIT1()  asm volatile("cp.async.wait_group 1;" ::: "memory")

// ================= scratch (referenced ONLY inside device code) =================
__device__ __align__(256) __half Xh_buf[MROWS * DIM];
__device__ __align__(256) __half Xl_buf[MROWS * DIM];
__device__ __align__(256) __half gh_buf[MROWS * DIM];
__device__ __align__(256) __half gl_buf[MROWS * DIM];
__device__ __align__(256) __half WGt_h[DIM * DIM];
__device__ __align__(256) __half Wkt_h[DIM * DIM];
__device__ __align__(256) float kw_buf[MROWS * DIM];
__device__ __align__(256) float g0_buf[BATCH * DIM];
__device__ __align__(256) float q0_part[32 * BATCH * DIM];
__device__ __align__(256) float q0_buf[BATCH * DIM];
__device__ __align__(256) float sc_buf[BATCH * HEADS * SEQ];
__device__ __align__(256) float row0_buf[BATCH * HEADS * SEQ];
__device__ __align__(256) float cos_tab[SEQ * 32];
__device__ __align__(256) float sin_tab[SEQ * 32];

// ================= RoPE tables =================
__global__ void rope_tables_kernel() {
    int s = blockIdx.x;
    int j = threadIdx.x;                 // 0..31
    float inv = powf(10000.0f, -((float)j) / 32.0f);
    float ang = (float)s * inv;
    cos_tab[s * 32 + j] = cosf(ang);
    sin_tab[s * 32 + j] = sinf(ang);
}

// ============ weight transpose + fp16 hi part only:  Wt[n][k] = fp16(W[k][n]) ============
template <int WHICH>
__global__ __launch_bounds__(256) void convW_kernel(const float* __restrict__ W)
{
    __half* Th = (WHICH == 0) ? WGt_h : Wkt_h;
    __shared__ float tile[32][33];
    int tx = threadIdx.x, ty = threadIdx.y;      // block (32, 8)
    int k0 = blockIdx.y * 32, n0 = blockIdx.x * 32;
    #pragma unroll
    for (int j = 0; j < 32; j += 8)
        tile[ty + j][tx] = W[(size_t)(k0 + ty + j) * DIM + n0 + tx];
    __syncthreads();
    #pragma unroll
    for (int j = 0; j < 32; j += 8) {
        float v = tile[tx][ty + j];
        Th[(size_t)(n0 + ty + j) * DIM + k0 + tx] = __float2half(v);
    }
}

// ============ X fp16 hi/lo split (elementwise) ============
__global__ __launch_bounds__(256) void convX_kernel(const float* __restrict__ X)
{
    int idx = blockIdx.x * 256 + threadIdx.x;    // over MROWS*DIM/4
    float4 v = ((const float4*)X)[idx];
    __half h0 = __float2half(v.x), h1 = __float2half(v.y);
    __half h2 = __float2half(v.z), h3 = __float2half(v.w);
    __half l0 = __float2half(v.x - __half2float(h0));
    __half l1 = __float2half(v.y - __half2float(h1));
    __half l2 = __float2half(v.z - __half2float(h2));
    __half l3 = __float2half(v.w - __half2float(h3));
    ((uint2*)Xh_buf)[idx] = make_uint2(pk_f16(h0, h1), pk_f16(h2, h3));
    ((uint2*)Xl_buf)[idx] = make_uint2(pk_f16(l0, l1), pk_f16(l2, l3));
}

// ================= mma.sync split-fp16 GEMM, 3-stage cp.async + ldmatrix =================
// C[4096,1024] = (Ah+Al) x Bh^T   (B stored [N][K] K-major, fp16 hi only), fp32 accum.
// 2 passes per acc: Ah*Bh + Al*Bh  (error = a*bl ~ 2^-12 rel per gemm).
// CTA tile 128x128, k-tile 32. 3 stages x 24KB (Ah,Al,Bh), 2 CTAs/SM.
// Stage layout (words): Ah[0..2047] Al[2048..4095] Bh[4096..6143]
#define STAGE_WORDS 6144      // 24KB per stage
#define NSTAGE 3

template <int PHASE>
__global__ __launch_bounds__(256, 2) void gemm_kernel(const float* __restrict__ bias)
{
    extern __shared__ __align__(16) uint32_t s32[];     // 3 x 6144 words
    const uint32_t sbu = smem_to_u32(s32);
    const int tid = threadIdx.x;
    const int wid = tid >> 5, lane = tid & 31;
    const int gID = lane >> 2, tig = lane & 3;
    const int m0 = blockIdx.y * 128, n0 = blockIdx.x * 128;
    const int wm = (wid & 3) * 32, wn = (wid >> 2) * 64;

    const __half* gptr[3];
    if (PHASE == 0) {
        gptr[0] = Xh_buf + (size_t)m0 * DIM;  gptr[1] = Xl_buf + (size_t)m0 * DIM;
        gptr[2] = WGt_h  + (size_t)n0 * DIM;
    } else {
        gptr[0] = gh_buf + (size_t)m0 * DIM;  gptr[1] = gl_buf + (size_t)m0 * DIM;
        gptr[2] = Wkt_h  + (size_t)n0 * DIM;
    }

    // stage copy: 1536 uint4 over 256 threads = 6 slots/thread
    int c_ten[6], c_row[6], c_ch[6];
    #pragma unroll
    for (int p = 0; p < 6; p++) {
        int cid = p * 256 + tid;           // 0..1535
        c_ten[p] = cid >> 9;               // 0,1,2 (512 chunks each)
        int rc = cid & 511;
        c_row[p] = rc >> 2;
        c_ch[p]  = rc & 3;
    }

    auto load_stage = [&](int buf, int t) {
        const int k0 = t * 32;
        #pragma unroll
        for (int p = 0; p < 6; p++) {
            int pc = c_ch[p] ^ ((c_row[p] >> 1) & 3);          // swizzled 16B chunk
            uint32_t sa = sbu + (buf * STAGE_WORDS + c_ten[p] * 2048) * 4
                              + c_row[p] * 64 + pc * 16;
            CP_ASYNC16(sa, gptr[c_ten[p]] + (size_t)c_row[p] * DIM + k0 + c_ch[p] * 8);
        }
    };

    // ldmatrix per-lane coords (mat = lane>>3):
    const int mat = lane >> 3;
    const int a_rr = (lane & 7) + ((mat & 1) << 3);
    const int a_cs = mat >> 1;
    const int b_rr = (lane & 7) + ((mat >> 1) << 3);
    const int b_cs = mat & 1;

    float acc[2][8][4] = {};

    load_stage(0, 0); CP_COMMIT();
    load_stage(1, 1); CP_COMMIT();

    for (int t = 0; t < 32; t++) {
        CP_WAIT1();                       // stage t resident (t+1 may be in flight)
        __syncthreads();
        if (t + 2 < 32) load_stage((t + 2) % NSTAGE, t + 2);
        CP_COMMIT();                      // commit every iter (empty at tail) for group math

        const uint32_t stAh = sbu + ((t % NSTAGE) * STAGE_WORDS) * 4;
        const uint32_t stAl = stAh + 2048 * 4;
        const uint32_t stBh = stAh + 4096 * 4;

        #pragma unroll
        for (int kb = 0; kb < 2; kb++) {
            // A fragments: 2 mi x 2 tensors
            uint32_t afh[2][4], afl[2][4];
            #pragma unroll
            for (int mi = 0; mi < 2; mi++) {
                int ra = wm + mi * 16 + a_rr;
                uint32_t ch = (uint32_t)(((kb << 1) + a_cs) ^ ((ra >> 1) & 3));
                uint32_t off = (uint32_t)ra * 64 + (ch << 4);
                ldsm4(stAh + off, afh[mi]);
                ldsm4(stAl + off, afl[mi]);
            }
            // B fragments for an nj-PAIR; two pass-major sweeps (8 mma each)
            #pragma unroll
            for (int njp = 0; njp < 2; njp++) {
                uint32_t bhq[2][4];
                #pragma unroll
                for (int q = 0; q < 2; q++) {
                    int rb = wn + (njp * 2 + q) * 16 + b_rr;
                    uint32_t ch = (uint32_t)(((kb << 1) + b_cs) ^ ((rb >> 1) & 3));
                    uint32_t off = (uint32_t)rb * 64 + (ch << 4);
                    ldsm4(stBh + off, bhq[q]);
                }
                // pass 1: afh x bh
                #pragma unroll
                for (int q = 0; q < 2; q++)
                    #pragma unroll
                    for (int hf = 0; hf < 2; hf++)
                        #pragma unroll
                        for (int mi = 0; mi < 2; mi++)
                            mma_f16(acc[mi][(njp * 2 + q) * 2 + hf], afh[mi], bhq[q] + hf * 2);
                // pass 2: afl x bh
                #pragma unroll
                for (int q = 0; q < 2; q++)
                    #pragma unroll
                    for (int hf = 0; hf < 2; hf++)
                        #pragma unroll
                        for (int mi = 0; mi < 2; mi++)
                            mma_f16(acc[mi][(njp * 2 + q) * 2 + hf], afl[mi], bhq[q] + hf * 2);
            }
        }
    }

    // ---- epilogue: acc[mi][j][*] -> rows wm+mi*16+gID(+8), cols wn+j*8+tig*2(,+1)
    #pragma unroll
    for (int mi = 0; mi < 2; mi++) {
        #pragma unroll
        for (int j = 0; j < 8; j++) {
            int n = n0 + wn + j * 8 + tig * 2;
            #pragma unroll
            for (int hh = 0; hh < 2; hh++) {
                int row = m0 + wm + mi * 16 + gID + hh * 8;
                float v0 = acc[mi][j][hh * 2]     + bias[n];
                float v1 = acc[mi][j][hh * 2 + 1] + bias[n + 1];
                if (PHASE == 0) {
                    __half h0 = __float2half(v0), h1 = __float2half(v1);
                    __half l0 = __float2half(v0 - __half2float(h0));
                    __half l1 = __float2half(v1 - __half2float(h1));
                    *(uint32_t*)&gh_buf[(size_t)row * DIM + n] = pk_f16(h0, h1);
                    *(uint32_t*)&gl_buf[(size_t)row * DIM + n] = pk_f16(l0, l1);
                    if ((row & (SEQ - 1)) == 0) {
                        g0_buf[(row >> 10) * DIM + n]     = v0;
                        g0_buf[(row >> 10) * DIM + n + 1] = v1;
                    }
                } else {
                    int s = row & (SEQ - 1);
                    int jj = (n & (DKH - 1)) >> 1;
                    float cs = cos_tab[s * 32 + jj];
                    float sn = sin_tab[s * 32 + jj];
                    *(float2*)&kw_buf[(size_t)row * DIM + n] =
                        make_float2(v0 * cs - v1 * sn, v1 * cs + v0 * sn);
                }
            }
        }
    }
}

// ============ q0 = g0 @ Wq (split-K x32 partials), fp32 ============
__global__ __launch_bounds__(256) void q0_part_kernel(const float* __restrict__ Wq)
{
    __shared__ float gs[32];
    int b = blockIdx.z, ks = blockIdx.y, cb = blockIdx.x;
    int col = cb * 256 + threadIdx.x;
    if (threadIdx.x < 32) gs[threadIdx.x] = g0_buf[b * DIM + ks * 32 + threadIdx.x];
    __syncthreads();
    float a = 0.f;
    #pragma unroll
    for (int i = 0; i < 32; i++)
        a += gs[i] * Wq[(size_t)(ks * 32 + i) * DIM + col];
    q0_part[(ks * BATCH + b) * DIM + col] = a;
}
__global__ __launch_bounds__(256) void q0_reduce_kernel(const float* __restrict__ bq)
{
    int idx = blockIdx.x * 256 + threadIdx.x;    // 0..4095
    int b = idx >> 10, col = idx & (DIM - 1);
    float a = bq[col];
    #pragma unroll
    for (int ks = 0; ks < 32; ks++) a += q0_part[(ks * BATCH + b) * DIM + col];
    q0_buf[idx] = a;
}

// ============ scores (parallel over 512 CTAs) ============
__global__ __launch_bounds__(256) void scores_kernel(const int* __restrict__ mask)
{
    int bh = blockIdx.y, seg = blockIdx.x;
    int b = bh >> 4, h = bh & 15;
    __shared__ float q0s[DKH];
    int tid = threadIdx.x;
    if (tid < DKH) q0s[tid] = q0_buf[b * DIM + h * DKH + tid];
    __syncthreads();
    int lane = tid & 31, warp = tid >> 5;
    #pragma unroll 4
    for (int i = 0; i < 16; i++) {
        int s = seg * 128 + i * 8 + warp;
        const float* kr = kw_buf + ((size_t)(b * SEQ + s)) * DIM + h * DKH;
        float v = q0s[lane] * kr[lane] + q0s[lane + 32] * kr[lane + 32];
        #pragma unroll
        for (int o = 16; o; o >>= 1) v += __shfl_down_sync(0xffffffffu, v, o);
        if (lane == 0) {
            float sv = v * 0.125f;   // 1/sqrt(64)
            if (mask[b * SEQ + s] == 0) sv = -1e9f;
            sc_buf[bh * SEQ + s] = sv;
        }
    }
}

// ============ softmax over 1024 ============
__global__ __launch_bounds__(256) void softmax_kernel()
{
    int bh = blockIdx.x;
    __shared__ float sc[SEQ];
    __shared__ float red[256];
    int tid = threadIdx.x;
    float m = -1e30f;
    for (int i = tid; i < SEQ; i += 256) { float v = sc_buf[bh * SEQ + i]; sc[i] = v; m = fmaxf(m, v); }
    red[tid] = m; __syncthreads();
    for (int o = 128; o; o >>= 1) { if (tid < o) red[tid] = fmaxf(red[tid], red[tid + o]); __syncthreads(); }
    m = red[0]; __syncthreads();
    float sum = 0.f;
    for (int i = tid; i < SEQ; i += 256) { float e = expf(sc[i] - m); sc[i] = e; sum += e; }
    red[tid] = sum; __syncthreads();
    for (int o = 128; o; o >>= 1) { if (tid < o) red[tid] += red[tid + o]; __syncthreads(); }
    float inv = 1.0f / red[0];
    for (int i = tid; i < SEQ; i += 256) row0_buf[bh * SEQ + i] = sc[i] * inv;
}

// ============ conv1d(k=3, 16->1024) + bias + relu ============
__global__ __launch_bounds__(256) void conv_kernel(const float* __restrict__ conv_w,
                                                   const float* __restrict__ conv_b,
                                                   float* __restrict__ out)
{
    int b  = blockIdx.z;
    int o0 = blockIdx.y * 64;
    int s0 = blockIdx.x * 512;
    __shared__ float ws[64 * 48];
    __shared__ float bs[64];
    int tid = threadIdx.x;
    for (int idx = tid; idx < 64 * 48; idx += 256) ws[idx] = conv_w[o0 * 48 + idx];
    if (tid < 64) bs[tid] = conv_b[o0 + tid];
    __syncthreads();
    int s = s0 + tid * 2;
    float r[16][4];
    #pragma unroll
    for (int i = 0; i < 16; i++) {
        const float* rp = row0_buf + (b * HEADS + i) * SEQ;
        r[i][0] = (s == 0) ? 0.f : rp[s - 1];
        r[i][1] = rp[s];
        r[i][2] = rp[s + 1];
        r[i][3] = (s + 2 > SEQ - 1) ? 0.f : rp[s + 2];
    }
    for (int o = 0; o < 64; o++) {
        float a0 = bs[o], a1 = bs[o];
        const float* w = &ws[o * 48];
        #pragma unroll
        for (int i = 0; i < 16; i++) {
            float w0 = w[i*3], w1 = w[i*3+1], w2 = w[i*3+2];
            a0 += r[i][0]*w0 + r[i][1]*w1 + r[i][2]*w2;
            a1 += r[i][1]*w0 + r[i][2]*w1 + r[i][3]*w2;
        }
        *(float2*)&out[((size_t)(b * DIM) + (o0 + o)) * SEQ + s] =
            make_float2(fmaxf(a0, 0.f), fmaxf(a1, 0.f));
    }
}

// ================= launch =================
#define GSMEM (NSTAGE * STAGE_WORDS * 4)   // 73728 bytes

extern "C" void kernel_launch(void* const* d_in, const int* in_sizes, int n_in,
                              void* d_out, int out_size)
{
    const float* X      = (const float*)d_in[0];
    const int*   mask   = (const int*)  d_in[1];
    const float* W_G    = (const float*)d_in[2];
    const float* b_G    = (const float*)d_in[3];
    const float* Wq     = (const float*)d_in[4];
    const float* bq     = (const float*)d_in[5];
    const float* Wk     = (const float*)d_in[6];
    const float* bk     = (const float*)d_in[7];
    const float* conv_w = (const float*)d_in[8];
    const float* conv_b = (const float*)d_in[9];
    float* out = (float*)d_out;

    cudaFuncSetAttribute(gemm_kernel<0>, cudaFuncAttributeMaxDynamicSharedMemorySize, GSMEM);
    cudaFuncSetAttribute(gemm_kernel<1>, cudaFuncAttributeMaxDynamicSharedMemorySize, GSMEM);

    // order chosen so gemm_kernel<0> is the 4th launch (the one ncu captures)
    convW_kernel<0><<<dim3(DIM/32, DIM/32), dim3(32, 8)>>>(W_G);
    convW_kernel<1><<<dim3(DIM/32, DIM/32), dim3(32, 8)>>>(Wk);
    convX_kernel<<<MROWS * DIM / 4 / 256, 256>>>(X);
    gemm_kernel<0><<<dim3(DIM/128, MROWS/128), 256, GSMEM>>>(b_G);
    rope_tables_kernel<<<SEQ, 32>>>();
    gemm_kernel<1><<<dim3(DIM/128, MROWS/128), 256, GSMEM>>>(bk);

    q0_part_kernel<<<dim3(DIM/256, 32, BATCH), 256>>>(Wq);
    q0_reduce_kernel<<<BATCH * DIM / 256, 256>>>(bq);
    scores_kernel<<<dim3(SEQ/128, BATCH*HEADS), 256>>>(mask);
    softmax_kernel<<<BATCH * HEADS, 256>>>();
    conv_kernel<<<dim3(SEQ/512, DIM/64, BATCH), 256>>>(conv_w, conv_b, out);
}

// round 16
// speedup vs baseline: 1.8415x; 1.3943x over previous
#include <cuda_runtime.h>
#include <cuda_fp16.h>
#include <math.h>
#include <stdint.h>

// Problem: B=4, S=1024, D=1024, H=16, DK=64
#define SEQ   1024
#define BATCH 4
#define DIM   1024
#define HEADS 16
#define DKH   64
#define MROWS (BATCH * SEQ)   // 4096

__device__ __forceinline__ uint32_t smem_to_u32(const void* p) {
    uint32_t a;
    asm("{ .reg .u64 t; cvta.to.shared.u64 t, %1; cvt.u32.u64 %0, t; }" : "=r"(a) : "l"(p));
    return a;
}
__device__ __forceinline__ uint32_t pk_f16(__half a, __half b) {
    return (uint32_t)__half_as_ushort(a) | ((uint32_t)__half_as_ushort(b) << 16);
}
__device__ __forceinline__ void mma_f16(float* d, const uint32_t* a, const uint32_t* b) {
    asm volatile("mma.sync.aligned.m16n8k16.row.col.f32.f16.f16.f32 "
        "{%0,%1,%2,%3}, {%4,%5,%6,%7}, {%8,%9}, {%0,%1,%2,%3};"
        : "+f"(d[0]), "+f"(d[1]), "+f"(d[2]), "+f"(d[3])
        : "r"(a[0]), "r"(a[1]), "r"(a[2]), "r"(a[3]), "r"(b[0]), "r"(b[1]));
}
__device__ __forceinline__ void ldsm4(uint32_t addr, uint32_t* r) {
    asm volatile("ldmatrix.sync.aligned.m8n8.x4.shared.b16 {%0,%1,%2,%3}, [%4];"
        : "=r"(r[0]), "=r"(r[1]), "=r"(r[2]), "=r"(r[3]) : "r"(addr));
}
#define CP_ASYNC16(saddr, gaddr) \
    asm volatile("cp.async.cg.shared.global [%0], [%1], 16;" :: "r"(saddr), "l"(gaddr) : "memory")
#define CP_COMMIT() asm volatile("cp.async.commit_group;" ::: "memory")
#define CP_WAIT1()  asm volatile("cp.async.wait_group 1;" ::: "memory")

// ================= scratch (referenced ONLY inside device code) =================
__device__ __align__(256) __half Xh_buf[MROWS * DIM];
__device__ __align__(256) __half gh_buf[MROWS * DIM];
__device__ __align__(256) __half WGt_h[DIM * DIM];
__device__ __align__(256) __half Wkt_h[DIM * DIM];
__device__ __align__(256) float kw_buf[MROWS * DIM];
__device__ __align__(256) float g0_buf[BATCH * DIM];
__device__ __align__(256) float q0_part[32 * BATCH * DIM];
__device__ __align__(256) float q0_buf[BATCH * DIM];
__device__ __align__(256) float sc_buf[BATCH * HEADS * SEQ];
__device__ __align__(256) float row0_buf[BATCH * HEADS * SEQ];
__device__ __align__(256) float cos_tab[SEQ * 32];
__device__ __align__(256) float sin_tab[SEQ * 32];

// ================= RoPE tables =================
__global__ void rope_tables_kernel() {
    int s = blockIdx.x;
    int j = threadIdx.x;                 // 0..31
    float inv = powf(10000.0f, -((float)j) / 32.0f);
    float ang = (float)s * inv;
    cos_tab[s * 32 + j] = cosf(ang);
    sin_tab[s * 32 + j] = sinf(ang);
}

// ============ weight transpose + fp16:  Wt[n][k] = fp16(W[k][n]) ============
template <int WHICH>
__global__ __launch_bounds__(256) void convW_kernel(const float* __restrict__ W)
{
    __half* Th = (WHICH == 0) ? WGt_h : Wkt_h;
    __shared__ float tile[32][33];
    int tx = threadIdx.x, ty = threadIdx.y;      // block (32, 8)
    int k0 = blockIdx.y * 32, n0 = blockIdx.x * 32;
    #pragma unroll
    for (int j = 0; j < 32; j += 8)
        tile[ty + j][tx] = W[(size_t)(k0 + ty + j) * DIM + n0 + tx];
    __syncthreads();
    #pragma unroll
    for (int j = 0; j < 32; j += 8) {
        float v = tile[tx][ty + j];
        Th[(size_t)(n0 + ty + j) * DIM + k0 + tx] = __float2half(v);
    }
}

// ============ X fp16 convert (elementwise) ============
__global__ __launch_bounds__(256) void convX_kernel(const float* __restrict__ X)
{
    int idx = blockIdx.x * 256 + threadIdx.x;    // over MROWS*DIM/4
    float4 v = ((const float4*)X)[idx];
    ((uint2*)Xh_buf)[idx] = make_uint2(pk_f16(__float2half(v.x), __float2half(v.y)),
                                       pk_f16(__float2half(v.z), __float2half(v.w)));
}

// ================= mma.sync fp16 GEMM, 3-stage cp.async + ldmatrix =================
// C[4096,1024] = A x B^T  (B stored [N][K] K-major, fp16), fp32 accum, single pass.
// CTA tile 128x128, k-tile 32. 3 stages x 16KB (A,B), 2 CTAs/SM.
// Stage layout (words): A[0..2047] B[2048..4095]
#define STAGE_WORDS 4096      // 16KB per stage
#define NSTAGE 3

template <int PHASE>
__global__ __launch_bounds__(256, 2) void gemm_kernel(const float* __restrict__ bias)
{
    extern __shared__ __align__(16) uint32_t s32[];     // 3 x 4096 words
    const uint32_t sbu = smem_to_u32(s32);
    const int tid = threadIdx.x;
    const int wid = tid >> 5, lane = tid & 31;
    const int gID = lane >> 2, tig = lane & 3;
    const int m0 = blockIdx.y * 128, n0 = blockIdx.x * 128;
    const int wm = (wid & 3) * 32, wn = (wid >> 2) * 64;

    const __half* gptr[2];
    if (PHASE == 0) {
        gptr[0] = Xh_buf + (size_t)m0 * DIM;
        gptr[1] = WGt_h  + (size_t)n0 * DIM;
    } else {
        gptr[0] = gh_buf + (size_t)m0 * DIM;
        gptr[1] = Wkt_h  + (size_t)n0 * DIM;
    }

    // stage copy: 1024 uint4 over 256 threads = 4 slots/thread
    int c_ten[4], c_row[4], c_ch[4];
    #pragma unroll
    for (int p = 0; p < 4; p++) {
        int cid = p * 256 + tid;           // 0..1023
        c_ten[p] = cid >> 9;               // 0,1 (512 chunks each)
        int rc = cid & 511;
        c_row[p] = rc >> 2;
        c_ch[p]  = rc & 3;
    }

    auto load_stage = [&](int buf, int t) {
        const int k0 = t * 32;
        #pragma unroll
        for (int p = 0; p < 4; p++) {
            int pc = c_ch[p] ^ ((c_row[p] >> 1) & 3);          // swizzled 16B chunk
            uint32_t sa = sbu + (buf * STAGE_WORDS + c_ten[p] * 2048) * 4
                              + c_row[p] * 64 + pc * 16;
            CP_ASYNC16(sa, gptr[c_ten[p]] + (size_t)c_row[p] * DIM + k0 + c_ch[p] * 8);
        }
    };

    // ldmatrix per-lane coords (mat = lane>>3):
    const int mat = lane >> 3;
    const int a_rr = (lane & 7) + ((mat & 1) << 3);
    const int a_cs = mat >> 1;
    const int b_rr = (lane & 7) + ((mat >> 1) << 3);
    const int b_cs = mat & 1;

    float acc[2][8][4] = {};

    load_stage(0, 0); CP_COMMIT();
    load_stage(1, 1); CP_COMMIT();

    for (int t = 0; t < 32; t++) {
        CP_WAIT1();                       // stage t resident (t+1 may be in flight)
        __syncthreads();
        if (t + 2 < 32) load_stage((t + 2) % NSTAGE, t + 2);
        CP_COMMIT();                      // commit every iter (empty at tail) for group math

        const uint32_t stA = sbu + ((t % NSTAGE) * STAGE_WORDS) * 4;
        const uint32_t stB = stA + 2048 * 4;

        #pragma unroll
        for (int kb = 0; kb < 2; kb++) {
            // A fragments: 2 mi
            uint32_t af[2][4];
            #pragma unroll
            for (int mi = 0; mi < 2; mi++) {
                int ra = wm + mi * 16 + a_rr;
                uint32_t ch = (uint32_t)(((kb << 1) + a_cs) ^ ((ra >> 1) & 3));
                ldsm4(stA + (uint32_t)ra * 64 + (ch << 4), af[mi]);
            }
            // B fragments per nj-pair; one sweep of 8 mma each
            #pragma unroll
            for (int njp = 0; njp < 2; njp++) {
                uint32_t bq[2][4];
                #pragma unroll
                for (int q = 0; q < 2; q++) {
                    int rb = wn + (njp * 2 + q) * 16 + b_rr;
                    uint32_t ch = (uint32_t)(((kb << 1) + b_cs) ^ ((rb >> 1) & 3));
                    ldsm4(stB + (uint32_t)rb * 64 + (ch << 4), bq[q]);
                }
                #pragma unroll
                for (int q = 0; q < 2; q++)
                    #pragma unroll
                    for (int hf = 0; hf < 2; hf++)
                        #pragma unroll
                        for (int mi = 0; mi < 2; mi++)
                            mma_f16(acc[mi][(njp * 2 + q) * 2 + hf], af[mi], bq[q] + hf * 2);
            }
        }
    }

    // ---- epilogue: acc[mi][j][*] -> rows wm+mi*16+gID(+8), cols wn+j*8+tig*2(,+1)
    #pragma unroll
    for (int mi = 0; mi < 2; mi++) {
        #pragma unroll
        for (int j = 0; j < 8; j++) {
            int n = n0 + wn + j * 8 + tig * 2;
            #pragma unroll
            for (int hh = 0; hh < 2; hh++) {
                int row = m0 + wm + mi * 16 + gID + hh * 8;
                float v0 = acc[mi][j][hh * 2]     + bias[n];
                float v1 = acc[mi][j][hh * 2 + 1] + bias[n + 1];
                if (PHASE == 0) {
                    *(uint32_t*)&gh_buf[(size_t)row * DIM + n] =
                        pk_f16(__float2half(v0), __float2half(v1));
                    if ((row & (SEQ - 1)) == 0) {
                        g0_buf[(row >> 10) * DIM + n]     = v0;
                        g0_buf[(row >> 10) * DIM + n + 1] = v1;
                    }
                } else {
                    int s = row & (SEQ - 1);
                    int jj = (n & (DKH - 1)) >> 1;
                    float cs = cos_tab[s * 32 + jj];
                    float sn = sin_tab[s * 32 + jj];
                    *(float2*)&kw_buf[(size_t)row * DIM + n] =
                        make_float2(v0 * cs - v1 * sn, v1 * cs + v0 * sn);
                }
            }
        }
    }
}

// ============ q0 = g0 @ Wq (split-K x32 partials), fp32 ============
__global__ __launch_bounds__(256) void q0_part_kernel(const float* __restrict__ Wq)
{
    __shared__ float gs[32];
    int b = blockIdx.z, ks = blockIdx.y, cb = blockIdx.x;
    int col = cb * 256 + threadIdx.x;
    if (threadIdx.x < 32) gs[threadIdx.x] = g0_buf[b * DIM + ks * 32 + threadIdx.x];
    __syncthreads();
    float a = 0.f;
    #pragma unroll
    for (int i = 0; i < 32; i++)
        a += gs[i] * Wq[(size_t)(ks * 32 + i) * DIM + col];
    q0_part[(ks * BATCH + b) * DIM + col] = a;
}
__global__ __launch_bounds__(256) void q0_reduce_kernel(const float* __restrict__ bq)
{
    int idx = blockIdx.x * 256 + threadIdx.x;    // 0..4095
    int b = idx >> 10, col = idx & (DIM - 1);
    float a = bq[col];
    #pragma unroll
    for (int ks = 0; ks < 32; ks++) a += q0_part[(ks * BATCH + b) * DIM + col];
    q0_buf[idx] = a;
}

// ============ scores (parallel over 512 CTAs) ============
__global__ __launch_bounds__(256) void scores_kernel(const int* __restrict__ mask)
{
    int bh = blockIdx.y, seg = blockIdx.x;
    int b = bh >> 4, h = bh & 15;
    __shared__ float q0s[DKH];
    int tid = threadIdx.x;
    if (tid < DKH) q0s[tid] = q0_buf[b * DIM + h * DKH + tid];
    __syncthreads();
    int lane = tid & 31, warp = tid >> 5;
    #pragma unroll 4
    for (int i = 0; i < 16; i++) {
        int s = seg * 128 + i * 8 + warp;
        const float* kr = kw_buf + ((size_t)(b * SEQ + s)) * DIM + h * DKH;
        float v = q0s[lane] * kr[lane] + q0s[lane + 32] * kr[lane + 32];
        #pragma unroll
        for (int o = 16; o; o >>= 1) v += __shfl_down_sync(0xffffffffu, v, o);
        if (lane == 0) {
            float sv = v * 0.125f;   // 1/sqrt(64)
            if (mask[b * SEQ + s] == 0) sv = -1e9f;
            sc_buf[bh * SEQ + s] = sv;
        }
    }
}

// ============ softmax over 1024 ============
__global__ __launch_bounds__(256) void softmax_kernel()
{
    int bh = blockIdx.x;
    __shared__ float sc[SEQ];
    __shared__ float red[256];
    int tid = threadIdx.x;
    float m = -1e30f;
    for (int i = tid; i < SEQ; i += 256) { float v = sc_buf[bh * SEQ + i]; sc[i] = v; m = fmaxf(m, v); }
    red[tid] = m; __syncthreads();
    for (int o = 128; o; o >>= 1) { if (tid < o) red[tid] = fmaxf(red[tid], red[tid + o]); __syncthreads(); }
    m = red[0]; __syncthreads();
    float sum = 0.f;
    for (int i = tid; i < SEQ; i += 256) { float e = expf(sc[i] - m); sc[i] = e; sum += e; }
    red[tid] = sum; __syncthreads();
    for (int o = 128; o; o >>= 1) { if (tid < o) red[tid] += red[tid + o]; __syncthreads(); }
    float inv = 1.0f / red[0];
    for (int i = tid; i < SEQ; i += 256) row0_buf[bh * SEQ + i] = sc[i] * inv;
}

// ============ conv1d(k=3, 16->1024) + bias + relu ============
__global__ __launch_bounds__(256) void conv_kernel(const float* __restrict__ conv_w,
                                                   const float* __restrict__ conv_b,
                                                   float* __restrict__ out)
{
    int b  = blockIdx.z;
    int o0 = blockIdx.y * 64;
    int s0 = blockIdx.x * 512;
    __shared__ float ws[64 * 48];
    __shared__ float bs[64];
    int tid = threadIdx.x;
    for (int idx = tid; idx < 64 * 48; idx += 256) ws[idx] = conv_w[o0 * 48 + idx];
    if (tid < 64) bs[tid] = conv_b[o0 + tid];
    __syncthreads();
    int s = s0 + tid * 2;
    float r[16][4];
    #pragma unroll
    for (int i = 0; i < 16; i++) {
        const float* rp = row0_buf + (b * HEADS + i) * SEQ;
        r[i][0] = (s == 0) ? 0.f : rp[s - 1];
        r[i][1] = rp[s];
        r[i][2] = rp[s + 1];
        r[i][3] = (s + 2 > SEQ - 1) ? 0.f : rp[s + 2];
    }
    for (int o = 0; o < 64; o++) {
        float a0 = bs[o], a1 = bs[o];
        const float* w = &ws[o * 48];
        #pragma unroll
        for (int i = 0; i < 16; i++) {
            float w0 = w[i*3], w1 = w[i*3+1], w2 = w[i*3+2];
            a0 += r[i][0]*w0 + r[i][1]*w1 + r[i][2]*w2;
            a1 += r[i][1]*w0 + r[i][2]*w1 + r[i][3]*w2;
        }
        *(float2*)&out[((size_t)(b * DIM) + (o0 + o)) * SEQ + s] =
            make_float2(fmaxf(a0, 0.f), fmaxf(a1, 0.f));
    }
}

// ================= launch =================
#define GSMEM (NSTAGE * STAGE_WORDS * 4)   // 49152 bytes

extern "C" void kernel_launch(void* const* d_in, const int* in_sizes, int n_in,
                              void* d_out, int out_size)
{
    const float* X      = (const float*)d_in[0];
    const int*   mask   = (const int*)  d_in[1];
    const float* W_G    = (const float*)d_in[2];
    const float* b_G    = (const float*)d_in[3];
    const float* Wq     = (const float*)d_in[4];
    const float* bq     = (const float*)d_in[5];
    const float* Wk     = (const float*)d_in[6];
    const float* bk     = (const float*)d_in[7];
    const float* conv_w = (const float*)d_in[8];
    const float* conv_b = (const float*)d_in[9];
    float* out = (float*)d_out;

    cudaFuncSetAttribute(gemm_kernel<0>, cudaFuncAttributeMaxDynamicSharedMemorySize, GSMEM);
    cudaFuncSetAttribute(gemm_kernel<1>, cudaFuncAttributeMaxDynamicSharedMemorySize, GSMEM);

    // order chosen so gemm_kernel<0> is the 4th launch (the one ncu captures)
    convW_kernel<0><<<dim3(DIM/32, DIM/32), dim3(32, 8)>>>(W_G);
    convW_kernel<1><<<dim3(DIM/32, DIM/32), dim3(32, 8)>>>(Wk);
    convX_kernel<<<MROWS * DIM / 4 / 256, 256>>>(X);
    gemm_kernel<0><<<dim3(DIM/128, MROWS/128), 256, GSMEM>>>(b_G);
    rope_tables_kernel<<<SEQ, 32>>>();
    gemm_kernel<1><<<dim3(DIM/128, MROWS/128), 256, GSMEM>>>(bk);

    q0_part_kernel<<<dim3(DIM/256, 32, BATCH), 256>>>(Wq);
    q0_reduce_kernel<<<BATCH * DIM / 256, 256>>>(bq);
    scores_kernel<<<dim3(SEQ/128, BATCH*HEADS), 256>>>(mask);
    softmax_kernel<<<BATCH * HEADS, 256>>>();
    conv_kernel<<<dim3(SEQ/512, DIM/64, BATCH), 256>>>(conv_w, conv_b, out);
}

// round 17
// speedup vs baseline: 2.0351x; 1.1051x over previous
#include <cuda_runtime.h>
#include <cuda_fp16.h>
#include <math.h>
#include <stdint.h>

// Problem: B=4, S=1024, D=1024, H=16, DK=64
#define SEQ   1024
#define BATCH 4
#define DIM   1024
#define HEADS 16
#define DKH   64
#define MROWS (BATCH * SEQ)   // 4096

__device__ __forceinline__ uint32_t smem_to_u32(const void* p) {
    uint32_t a;
    asm("{ .reg .u64 t; cvta.to.shared.u64 t, %1; cvt.u32.u64 %0, t; }" : "=r"(a) : "l"(p));
    return a;
}
__device__ __forceinline__ uint32_t pk_f16(__half a, __half b) {
    return (uint32_t)__half_as_ushort(a) | ((uint32_t)__half_as_ushort(b) << 16);
}
__device__ __forceinline__ void mma_f16(float* d, const uint32_t* a, const uint32_t* b) {
    asm volatile("mma.sync.aligned.m16n8k16.row.col.f32.f16.f16.f32 "
        "{%0,%1,%2,%3}, {%4,%5,%6,%7}, {%8,%9}, {%0,%1,%2,%3};"
        : "+f"(d[0]), "+f"(d[1]), "+f"(d[2]), "+f"(d[3])
        : "r"(a[0]), "r"(a[1]), "r"(a[2]), "r"(a[3]), "r"(b[0]), "r"(b[1]));
}
__device__ __forceinline__ void ldsm4(uint32_t addr, uint32_t* r) {
    asm volatile("ldmatrix.sync.aligned.m8n8.x4.shared.b16 {%0,%1,%2,%3}, [%4];"
        : "=r"(r[0]), "=r"(r[1]), "=r"(r[2]), "=r"(r[3]) : "r"(addr));
}
#define CP_ASYNC16(saddr, gaddr) \
    asm volatile("cp.async.cg.shared.global [%0], [%1], 16;" :: "r"(saddr), "l"(gaddr) : "memory")
#define CP_COMMIT() asm volatile("cp.async.commit_group;" ::: "memory")
#define CP_WAIT1()  asm volatile("cp.async.wait_group 1;" ::: "memory")

// ================= scratch (referenced ONLY inside device code) =================
__device__ __align__(256) __half Xh_buf[MROWS * DIM];
__device__ __align__(256) __half gh_buf[MROWS * DIM];
__device__ __align__(256) __half WGt_h[DIM * DIM];
__device__ __align__(256) __half Wkt_h[DIM * DIM];
__device__ __align__(256) float kw_buf[MROWS * DIM];
__device__ __align__(256) float g0_buf[BATCH * DIM];
__device__ __align__(256) float q0_part[32 * BATCH * DIM];
__device__ __align__(256) float sc_buf[BATCH * HEADS * SEQ];
__device__ __align__(256) float row0_buf[BATCH * HEADS * SEQ];
__device__ __align__(256) float cos_tab[SEQ * 32];
__device__ __align__(256) float sin_tab[SEQ * 32];

// ============ weight transpose + fp16 (both weights, z selects) ============
__global__ __launch_bounds__(256) void convW_kernel(const float* __restrict__ W_G,
                                                    const float* __restrict__ Wk)
{
    const float* W = (blockIdx.z == 0) ? W_G : Wk;
    __half* Th     = (blockIdx.z == 0) ? WGt_h : Wkt_h;
    __shared__ float tile[32][33];
    int tx = threadIdx.x, ty = threadIdx.y;      // block (32, 8)
    int k0 = blockIdx.y * 32, n0 = blockIdx.x * 32;
    #pragma unroll
    for (int j = 0; j < 32; j += 8)
        tile[ty + j][tx] = W[(size_t)(k0 + ty + j) * DIM + n0 + tx];
    __syncthreads();
    #pragma unroll
    for (int j = 0; j < 32; j += 8) {
        float v = tile[tx][ty + j];
        Th[(size_t)(n0 + ty + j) * DIM + k0 + tx] = __float2half(v);
    }
}

// ============ X fp16 convert + RoPE tables (folded in) ============
__global__ __launch_bounds__(256) void convX_kernel(const float* __restrict__ X)
{
    int idx = blockIdx.x * 256 + threadIdx.x;    // over MROWS*DIM/4
    float4 v = ((const float4*)X)[idx];
    ((uint2*)Xh_buf)[idx] = make_uint2(pk_f16(__float2half(v.x), __float2half(v.y)),
                                       pk_f16(__float2half(v.z), __float2half(v.w)));
    if (blockIdx.x < SEQ && threadIdx.x < 32) {
        int s = blockIdx.x, j = threadIdx.x;
        float inv = powf(10000.0f, -((float)j) / 32.0f);
        float ang = (float)s * inv;
        cos_tab[s * 32 + j] = cosf(ang);
        sin_tab[s * 32 + j] = sinf(ang);
    }
}

// ================= mma.sync fp16 GEMM, 3-stage cp.async + ldmatrix, k-tile 64 =================
// C[4096,1024] = A x B^T  (B stored [N][K] K-major, fp16), fp32 accum, single pass.
// CTA tile 128x128, k-tile 64 (16 outer iters). 3 stages x 32KB, 2 CTAs/SM.
// Rows are 128B (64 halfs); 16B chunks swizzled pc = ch ^ (row & 7)  -> conflict-free ldmatrix.
// Stage layout (words): A[0..4095] B[4096..8191]
#define STAGE_WORDS 8192      // 32KB per stage
#define NSTAGE 3

template <int PHASE>
__global__ __launch_bounds__(256, 2) void gemm_kernel(const float* __restrict__ bias)
{
    extern __shared__ __align__(16) uint32_t s32[];     // 3 x 8192 words
    const uint32_t sbu = smem_to_u32(s32);
    const int tid = threadIdx.x;
    const int wid = tid >> 5, lane = tid & 31;
    const int gID = lane >> 2, tig = lane & 3;
    const int m0 = blockIdx.y * 128, n0 = blockIdx.x * 128;
    const int wm = (wid & 3) * 32, wn = (wid >> 2) * 64;

    const __half* gptr[2];
    if (PHASE == 0) {
        gptr[0] = Xh_buf + (size_t)m0 * DIM;
        gptr[1] = WGt_h  + (size_t)n0 * DIM;
    } else {
        gptr[0] = gh_buf + (size_t)m0 * DIM;
        gptr[1] = Wkt_h  + (size_t)n0 * DIM;
    }

    // stage copy: 2048 x 16B chunks over 256 threads = 8 slots/thread (computed inline)
    auto load_stage = [&](int buf, int t) {
        const int k0 = t * 64;
        #pragma unroll
        for (int p = 0; p < 8; p++) {
            int cid = p * 256 + tid;           // 0..2047
            int ten = cid >> 10;               // 0,1 (1024 chunks each)
            int rc  = cid & 1023;
            int row = rc >> 3, ch = rc & 7;
            int pc  = ch ^ (row & 7);          // swizzled 16B chunk within 128B row
            uint32_t sa = sbu + (buf * STAGE_WORDS + ten * 4096) * 4 + row * 128 + pc * 16;
            CP_ASYNC16(sa, gptr[ten] + (size_t)row * DIM + k0 + ch * 8);
        }
    };

    // ldmatrix per-lane coords (mat = lane>>3):
    const int mat = lane >> 3;
    const int a_rr = (lane & 7) + ((mat & 1) << 3);
    const int a_cs = mat >> 1;
    const int b_rr = (lane & 7) + ((mat >> 1) << 3);
    const int b_cs = mat & 1;

    float acc[2][8][4] = {};

    load_stage(0, 0); CP_COMMIT();
    load_stage(1, 1); CP_COMMIT();

    for (int t = 0; t < 16; t++) {
        CP_WAIT1();                       // stage t resident (t+1 may be in flight)
        __syncthreads();
        if (t + 2 < 16) load_stage((t + 2) % NSTAGE, t + 2);
        CP_COMMIT();                      // commit every iter (empty at tail) for group math

        const uint32_t stA = sbu + ((t % NSTAGE) * STAGE_WORDS) * 4;
        const uint32_t stB = stA + 4096 * 4;

        #pragma unroll
        for (int kb = 0; kb < 4; kb++) {
            // A fragments: 2 mi
            uint32_t af[2][4];
            #pragma unroll
            for (int mi = 0; mi < 2; mi++) {
                int ra = wm + mi * 16 + a_rr;
                uint32_t ch = (uint32_t)(((kb << 1) + a_cs) ^ (ra & 7));
                ldsm4(stA + (uint32_t)ra * 128 + (ch << 4), af[mi]);
            }
            // B fragments per nj-pair; one sweep of 8 mma each
            #pragma unroll
            for (int njp = 0; njp < 2; njp++) {
                uint32_t bq[2][4];
                #pragma unroll
                for (int q = 0; q < 2; q++) {
                    int rb = wn + (njp * 2 + q) * 16 + b_rr;
                    uint32_t ch = (uint32_t)(((kb << 1) + b_cs) ^ (rb & 7));
                    ldsm4(stB + (uint32_t)rb * 128 + (ch << 4), bq[q]);
                }
                #pragma unroll
                for (int q = 0; q < 2; q++)
                    #pragma unroll
                    for (int hf = 0; hf < 2; hf++)
                        #pragma unroll
                        for (int mi = 0; mi < 2; mi++)
                            mma_f16(acc[mi][(njp * 2 + q) * 2 + hf], af[mi], bq[q] + hf * 2);
            }
        }
    }

    // ---- epilogue: acc[mi][j][*] -> rows wm+mi*16+gID(+8), cols wn+j*8+tig*2(,+1)
    #pragma unroll
    for (int mi = 0; mi < 2; mi++) {
        #pragma unroll
        for (int j = 0; j < 8; j++) {
            int n = n0 + wn + j * 8 + tig * 2;
            #pragma unroll
            for (int hh = 0; hh < 2; hh++) {
                int row = m0 + wm + mi * 16 + gID + hh * 8;
                float v0 = acc[mi][j][hh * 2]     + bias[n];
                float v1 = acc[mi][j][hh * 2 + 1] + bias[n + 1];
                if (PHASE == 0) {
                    *(uint32_t*)&gh_buf[(size_t)row * DIM + n] =
                        pk_f16(__float2half(v0), __float2half(v1));
                    if ((row & (SEQ - 1)) == 0) {
                        g0_buf[(row >> 10) * DIM + n]     = v0;
                        g0_buf[(row >> 10) * DIM + n + 1] = v1;
                    }
                } else {
                    int s = row & (SEQ - 1);
                    int jj = (n & (DKH - 1)) >> 1;
                    float cs = cos_tab[s * 32 + jj];
                    float sn = sin_tab[s * 32 + jj];
                    *(float2*)&kw_buf[(size_t)row * DIM + n] =
                        make_float2(v0 * cs - v1 * sn, v1 * cs + v0 * sn);
                }
            }
        }
    }
}

// ============ q0 partials: q0_part[ks][b][col] = sum_{i<32} g0[b][ks*32+i] * Wq[.][col] ============
__global__ __launch_bounds__(256) void q0_part_kernel(const float* __restrict__ Wq)
{
    __shared__ float gs[32];
    int b = blockIdx.z, ks = blockIdx.y, cb = blockIdx.x;
    int col = cb * 256 + threadIdx.x;
    if (threadIdx.x < 32) gs[threadIdx.x] = g0_buf[b * DIM + ks * 32 + threadIdx.x];
    __syncthreads();
    float a = 0.f;
    #pragma unroll
    for (int i = 0; i < 32; i++)
        a += gs[i] * Wq[(size_t)(ks * 32 + i) * DIM + col];
    q0_part[(ks * BATCH + b) * DIM + col] = a;
}

// ============ scores (fused q0 reduce; parallel over 512 CTAs) ============
__global__ __launch_bounds__(256) void scores_kernel(const int* __restrict__ mask,
                                                     const float* __restrict__ bq)
{
    int bh = blockIdx.y, seg = blockIdx.x;
    int b = bh >> 4, h = bh & 15;
    __shared__ float q0s[DKH];
    int tid = threadIdx.x;
    if (tid < DKH) {
        int col = h * DKH + tid;
        float a = bq[col];
        #pragma unroll
        for (int ks = 0; ks < 32; ks++) a += q0_part[(ks * BATCH + b) * DIM + col];
        q0s[tid] = a;
    }
    __syncthreads();
    int lane = tid & 31, warp = tid >> 5;
    #pragma unroll 4
    for (int i = 0; i < 16; i++) {
        int s = seg * 128 + i * 8 + warp;
        const float* kr = kw_buf + ((size_t)(b * SEQ + s)) * DIM + h * DKH;
        float v = q0s[lane] * kr[lane] + q0s[lane + 32] * kr[lane + 32];
        #pragma unroll
        for (int o = 16; o; o >>= 1) v += __shfl_down_sync(0xffffffffu, v, o);
        if (lane == 0) {
            float sv = v * 0.125f;   // 1/sqrt(64)
            if (mask[b * SEQ + s] == 0) sv = -1e9f;
            sc_buf[bh * SEQ + s] = sv;
        }
    }
}

// ============ softmax over 1024 ============
__global__ __launch_bounds__(256) void softmax_kernel()
{
    int bh = blockIdx.x;
    __shared__ float sc[SEQ];
    __shared__ float red[256];
    int tid = threadIdx.x;
    float m = -1e30f;
    for (int i = tid; i < SEQ; i += 256) { float v = sc_buf[bh * SEQ + i]; sc[i] = v; m = fmaxf(m, v); }
    red[tid] = m; __syncthreads();
    for (int o = 128; o; o >>= 1) { if (tid < o) red[tid] = fmaxf(red[tid], red[tid + o]); __syncthreads(); }
    m = red[0]; __syncthreads();
    float sum = 0.f;
    for (int i = tid; i < SEQ; i += 256) { float e = expf(sc[i] - m); sc[i] = e; sum += e; }
    red[tid] = sum; __syncthreads();
    for (int o = 128; o; o >>= 1) { if (tid < o) red[tid] += red[tid + o]; __syncthreads(); }
    float inv = 1.0f / red[0];
    for (int i = tid; i < SEQ; i += 256) row0_buf[bh * SEQ + i] = sc[i] * inv;
}

// ============ conv1d(k=3, 16->1024) + bias + relu ============
__global__ __launch_bounds__(256) void conv_kernel(const float* __restrict__ conv_w,
                                                   const float* __restrict__ conv_b,
                                                   float* __restrict__ out)
{
    int b  = blockIdx.z;
    int o0 = blockIdx.y * 64;
    int s0 = blockIdx.x * 512;
    __shared__ float ws[64 * 48];
    __shared__ float bs[64];
    int tid = threadIdx.x;
    for (int idx = tid; idx < 64 * 48; idx += 256) ws[idx] = conv_w[o0 * 48 + idx];
    if (tid < 64) bs[tid] = conv_b[o0 + tid];
    __syncthreads();
    int s = s0 + tid * 2;
    float r[16][4];
    #pragma unroll
    for (int i = 0; i < 16; i++) {
        const float* rp = row0_buf + (b * HEADS + i) * SEQ;
        r[i][0] = (s == 0) ? 0.f : rp[s - 1];
        r[i][1] = rp[s];
        r[i][2] = rp[s + 1];
        r[i][3] = (s + 2 > SEQ - 1) ? 0.f : rp[s + 2];
    }
    for (int o = 0; o < 64; o++) {
        float a0 = bs[o], a1 = bs[o];
        const float* w = &ws[o * 48];
        #pragma unroll
        for (int i = 0; i < 16; i++) {
            float w0 = w[i*3], w1 = w[i*3+1], w2 = w[i*3+2];
            a0 += r[i][0]*w0 + r[i][1]*w1 + r[i][2]*w2;
            a1 += r[i][1]*w0 + r[i][2]*w1 + r[i][3]*w2;
        }
        *(float2*)&out[((size_t)(b * DIM) + (o0 + o)) * SEQ + s] =
            make_float2(fmaxf(a0, 0.f), fmaxf(a1, 0.f));
    }
}

// ================= launch =================
#define GSMEM (NSTAGE * STAGE_WORDS * 4)   // 98304 bytes

extern "C" void kernel_launch(void* const* d_in, const int* in_sizes, int n_in,
                              void* d_out, int out_size)
{
    const float* X      = (const float*)d_in[0];
    const int*   mask   = (const int*)  d_in[1];
    const float* W_G    = (const float*)d_in[2];
    const float* b_G    = (const float*)d_in[3];
    const float* Wq     = (const float*)d_in[4];
    const float* bq     = (const float*)d_in[5];
    const float* Wk     = (const float*)d_in[6];
    const float* bk     = (const float*)d_in[7];
    const float* conv_w = (const float*)d_in[8];
    const float* conv_b = (const float*)d_in[9];
    float* out = (float*)d_out;

    cudaFuncSetAttribute(gemm_kernel<0>, cudaFuncAttributeMaxDynamicSharedMemorySize, GSMEM);
    cudaFuncSetAttribute(gemm_kernel<1>, cudaFuncAttributeMaxDynamicSharedMemorySize, GSMEM);

    convW_kernel<<<dim3(DIM/32, DIM/32, 2), dim3(32, 8)>>>(W_G, Wk);
    convX_kernel<<<MROWS * DIM / 4 / 256, 256>>>(X);
    gemm_kernel<0><<<dim3(DIM/128, MROWS/128), 256, GSMEM>>>(b_G);
    gemm_kernel<1><<<dim3(DIM/128, MROWS/128), 256, GSMEM>>>(bk);   // 4th launch (profiled)
    q0_part_kernel<<<dim3(DIM/256, 32, BATCH), 256>>>(Wq);
    scores_kernel<<<dim3(SEQ/128, BATCH*HEADS), 256>>>(mask, bq);
    softmax_kernel<<<BATCH * HEADS, 256>>>();
    conv_kernel<<<dim3(SEQ/512, DIM/64, BATCH), 256>>>(conv_w, conv_b, out);
}